// round 1
// baseline (speedup 1.0000x reference)
#include <cuda_runtime.h>
#include <cuda_bf16.h>
#include <math.h>

// Problem constants
#define BB 8
#define DD 512
#define SS 4096
#define FF 2048

// ---------------- static scratch (no allocations allowed) ----------------
__device__ float g_q [(size_t)BB * SS * DD];          // 64MB  [B,S,D]
__device__ float g_k [(size_t)BB * SS * DD];          // 64MB
__device__ float g_v [(size_t)BB * SS * DD];          // 64MB
__device__ float g_s [(size_t)BB * SS * SS];          // 512MB [B,S,S] scores/attn
__device__ float g_t1[(size_t)BB * SS * DD];          // 64MB  attn@v
__device__ float g_ao[(size_t)BB * SS * DD];          // 64MB  (attn@v)@Wo
__device__ float g_y [(size_t)BB * SS * DD];          // 64MB  residual1 / post (normed in place)
__device__ float g_h1[(size_t)BB * SS * FF];          // 256MB FFN hidden
__device__ float g_h2[(size_t)BB * SS * DD];          // 64MB  FFN out -> residual2 in place
__device__ double g_acc[32];                          // [stage(2)][batch(8)][sum,sumsq]

// ---------------- GEMM: C = A*B (+bias, +relu), batched ----------------
// AK: A stored K-major [K,M] (lda = row stride). else [M,K].
// BK: B stored K-major [K,N]. else [N,K].
// EPI: 0 none, 1 +bias, 2 relu(+bias)
#define TM 128
#define TN 128
#define TK 16

template <bool AK, bool BK, int EPI>
__global__ __launch_bounds__(256, 2)
void gemm_kernel(const float* __restrict__ A, const float* __restrict__ B,
                 const float* __restrict__ bias, float* __restrict__ C,
                 int M, int N, int K, int lda, int ldb, int ldc,
                 long long sA, long long sB, long long sC)
{
    __shared__ float As[TK][TM];
    __shared__ float Bs[TK][TN];

    const int bz = blockIdx.z;
    A += (long long)bz * sA;
    B += (long long)bz * sB;
    C += (long long)bz * sC;

    const int m0 = blockIdx.y * TM;
    const int n0 = blockIdx.x * TN;
    const int tid = threadIdx.x;
    const int r = tid >> 4;   // 0..15
    const int c = tid & 15;   // 0..15

    float acc[8][8];
#pragma unroll
    for (int i = 0; i < 8; i++)
#pragma unroll
        for (int j = 0; j < 8; j++) acc[i][j] = 0.f;

    for (int k0 = 0; k0 < K; k0 += TK) {
        // ---- load A tile ----
#pragma unroll
        for (int it = 0; it < 2; it++) {
            int idx = tid + it * 256;      // 0..511 float4 slots (2048 floats)
            if (AK) {
                int kk = idx >> 5;         // 0..15
                int mq = idx & 31;         // 0..31 (float4 across M)
                float4 va = *(const float4*)(A + (long long)(k0 + kk) * lda + m0 + mq * 4);
                *(float4*)(&As[kk][mq * 4]) = va;
            } else {
                int m  = idx >> 2;         // 0..127
                int kq = idx & 3;          // float4 across K
                float4 va = *(const float4*)(A + (long long)(m0 + m) * lda + k0 + kq * 4);
                As[kq * 4 + 0][m] = va.x;
                As[kq * 4 + 1][m] = va.y;
                As[kq * 4 + 2][m] = va.z;
                As[kq * 4 + 3][m] = va.w;
            }
        }
        // ---- load B tile ----
#pragma unroll
        for (int it = 0; it < 2; it++) {
            int idx = tid + it * 256;
            if (BK) {
                int kk = idx >> 5;
                int nq = idx & 31;
                float4 vb = *(const float4*)(B + (long long)(k0 + kk) * ldb + n0 + nq * 4);
                *(float4*)(&Bs[kk][nq * 4]) = vb;
            } else {
                int n  = idx >> 2;
                int kq = idx & 3;
                float4 vb = *(const float4*)(B + (long long)(n0 + n) * ldb + k0 + kq * 4);
                Bs[kq * 4 + 0][n] = vb.x;
                Bs[kq * 4 + 1][n] = vb.y;
                Bs[kq * 4 + 2][n] = vb.z;
                Bs[kq * 4 + 3][n] = vb.w;
            }
        }
        __syncthreads();

#pragma unroll
        for (int kk = 0; kk < TK; kk++) {
            float a[8], bv[8];
#pragma unroll
            for (int i = 0; i < 8; i++) a[i]  = As[kk][r * 8 + i];
#pragma unroll
            for (int j = 0; j < 8; j++) bv[j] = Bs[kk][c * 8 + j];
#pragma unroll
            for (int i = 0; i < 8; i++)
#pragma unroll
                for (int j = 0; j < 8; j++)
                    acc[i][j] = fmaf(a[i], bv[j], acc[i][j]);
        }
        __syncthreads();
    }

    // ---- epilogue ----
#pragma unroll
    for (int i = 0; i < 8; i++) {
        int m = m0 + r * 8 + i;
#pragma unroll
        for (int j = 0; j < 8; j += 4) {
            int n = n0 + c * 8 + j;
            float4 o;
            o.x = acc[i][j + 0];
            o.y = acc[i][j + 1];
            o.z = acc[i][j + 2];
            o.w = acc[i][j + 3];
            if (EPI >= 1) {
                o.x += bias[n + 0]; o.y += bias[n + 1];
                o.z += bias[n + 2]; o.w += bias[n + 3];
            }
            if (EPI == 2) {
                o.x = fmaxf(o.x, 0.f); o.y = fmaxf(o.y, 0.f);
                o.z = fmaxf(o.z, 0.f); o.w = fmaxf(o.w, 0.f);
            }
            *(float4*)(C + (long long)m * ldc + n) = o;
        }
    }
}

// ---------------- softmax over rows of g_s (in place, scaled) ----------------
__global__ void softmax_kernel(float* __restrict__ s, float scale)
{
    const long long row = blockIdx.x;                 // 0 .. B*S-1
    float4* p = (float4*)(s + row * SS);              // 1024 float4 per row
    const int tid = threadIdx.x;                      // 256 threads
    __shared__ float red[256];

    float4 v[4];
    float mx = -INFINITY;
#pragma unroll
    for (int ii = 0; ii < 4; ii++) {
        v[ii] = p[tid + ii * 256];
        mx = fmaxf(mx, fmaxf(fmaxf(v[ii].x, v[ii].y), fmaxf(v[ii].z, v[ii].w)));
    }
    red[tid] = mx; __syncthreads();
    for (int o = 128; o > 0; o >>= 1) {
        if (tid < o) red[tid] = fmaxf(red[tid], red[tid + o]);
        __syncthreads();
    }
    mx = red[0];
    __syncthreads();

    float sum = 0.f;
#pragma unroll
    for (int ii = 0; ii < 4; ii++) {
        v[ii].x = __expf((v[ii].x - mx) * scale);
        v[ii].y = __expf((v[ii].y - mx) * scale);
        v[ii].z = __expf((v[ii].z - mx) * scale);
        v[ii].w = __expf((v[ii].w - mx) * scale);
        sum += v[ii].x + v[ii].y + v[ii].z + v[ii].w;
    }
    red[tid] = sum; __syncthreads();
    for (int o = 128; o > 0; o >>= 1) {
        if (tid < o) red[tid] += red[tid + o];
        __syncthreads();
    }
    const float inv = 1.f / red[0];
#pragma unroll
    for (int ii = 0; ii < 4; ii++) {
        v[ii].x *= inv; v[ii].y *= inv; v[ii].z *= inv; v[ii].w *= inv;
        p[tid + ii * 256] = v[ii];
    }
}

// ---------------- reductions for the global norm ----------------
__device__ __forceinline__ void block_reduce_add2(float a, float b, int t, double* dst)
{
    __shared__ float sa[256], sb[256];
    sa[t] = a; sb[t] = b; __syncthreads();
    for (int o = 128; o > 0; o >>= 1) {
        if (t < o) { sa[t] += sa[t + o]; sb[t] += sb[t + o]; }
        __syncthreads();
    }
    if (t == 0) {
        atomicAdd(dst + 0, (double)sa[0]);
        atomicAdd(dst + 1, (double)sb[0]);
    }
}

__global__ void zero_acc_kernel()
{
    if (threadIdx.x < 32) g_acc[threadIdx.x] = 0.0;
}

// y[b,s,d] = x[b,d,s] + ao[b,s,d]; accumulate sum & sumsq per batch (stage 0)
__global__ void resid1_kernel(const float* __restrict__ x, const float* __restrict__ ao,
                              float* __restrict__ y)
{
    const int b  = blockIdx.z;
    const int s0 = blockIdx.x * 32;
    const int d0 = blockIdx.y * 32;
    __shared__ float xs[32][33];
    const int tx = threadIdx.x, ty = threadIdx.y;   // 32 x 8
    const int t = ty * 32 + tx;

    const float* xb = x + (long long)b * DD * SS;
#pragma unroll
    for (int i = 0; i < 32; i += 8)
        xs[ty + i][tx] = xb[(long long)(d0 + ty + i) * SS + s0 + tx];
    __syncthreads();

    float ls = 0.f, lq = 0.f;
#pragma unroll
    for (int i = 0; i < 32; i += 8) {
        long long off = ((long long)b * SS + s0 + ty + i) * DD + d0 + tx;
        float vv = ao[off] + xs[tx][ty + i];
        y[off] = vv;
        ls += vv;
        lq += vv * vv;
    }
    block_reduce_add2(ls, lq, t, g_acc + 2 * b);
}

// normalize y in place with stage-0 stats
__global__ void apply1_kernel(float* __restrict__ y)
{
    const int b = blockIdx.y;
    const double sum = g_acc[2 * b], sq = g_acc[2 * b + 1];
    const double NE = (double)SS * DD;
    const double mean = sum / NE;
    double var = sq - NE * mean * mean;
    if (var < 0.0) var = 0.0;
    const float inv = (float)(1.0 / (sqrt(var) + 1e-7));
    const float fm = (float)mean;

    float4* y4 = ((float4*)y) + (long long)b * (SS * DD / 4);
    const long long i = (long long)blockIdx.x * 256 + threadIdx.x;  // grid.x = 2048 exact
    float4 vv = y4[i];
    vv.x = (vv.x - fm) * inv; vv.y = (vv.y - fm) * inv;
    vv.z = (vv.z - fm) * inv; vv.w = (vv.w - fm) * inv;
    y4[i] = vv;
}

// h2 <- post + h2 ; accumulate stats (stage 1)
__global__ void resid2_kernel(const float* __restrict__ post, float* __restrict__ h2)
{
    const int b = blockIdx.y;
    const float4* p4 = ((const float4*)post) + (long long)b * (SS * DD / 4);
    float4*       h4 = ((float4*)h2)   + (long long)b * (SS * DD / 4);
    const long long i = (long long)blockIdx.x * 256 + threadIdx.x;
    float4 a = p4[i], cc = h4[i];
    a.x += cc.x; a.y += cc.y; a.z += cc.z; a.w += cc.w;
    h4[i] = a;
    float ls = a.x + a.y + a.z + a.w;
    float lq = a.x * a.x + a.y * a.y + a.z * a.z + a.w * a.w;
    block_reduce_add2(ls, lq, threadIdx.x, g_acc + 16 + 2 * b);
}

// out[b,d,s] = (y2[b,s,d] - mean) * inv   (stage-1 stats), transposed write
__global__ void apply2t_kernel(const float* __restrict__ y2, float* __restrict__ out)
{
    const int b = blockIdx.z;
    const double sum = g_acc[16 + 2 * b], sq = g_acc[16 + 2 * b + 1];
    const double NE = (double)SS * DD;
    const double mean = sum / NE;
    double var = sq - NE * mean * mean;
    if (var < 0.0) var = 0.0;
    const float inv = (float)(1.0 / (sqrt(var) + 1e-7));
    const float fm = (float)mean;

    const int s0 = blockIdx.x * 32;
    const int d0 = blockIdx.y * 32;
    __shared__ float ys[32][33];
    const int tx = threadIdx.x, ty = threadIdx.y;   // 32 x 8

#pragma unroll
    for (int i = 0; i < 32; i += 8)
        ys[ty + i][tx] = y2[((long long)b * SS + s0 + ty + i) * DD + d0 + tx];
    __syncthreads();
#pragma unroll
    for (int i = 0; i < 32; i += 8)
        out[((long long)b * DD + d0 + ty + i) * SS + s0 + tx] =
            (ys[tx][ty + i] - fm) * inv;
}

// ---------------- host-side orchestration ----------------
static float* sym(float* /*dummy*/, const void* symbol)
{
    void* p = nullptr;
    cudaGetSymbolAddress(&p, symbol);
    return (float*)p;
}

extern "C" void kernel_launch(void* const* d_in, const int* in_sizes, int n_in,
                              void* d_out, int out_size)
{
    const float* x  = (const float*)d_in[0];
    const float* Wq = (const float*)d_in[1];
    const float* Wk = (const float*)d_in[2];
    const float* Wv = (const float*)d_in[3];
    const float* Wo = (const float*)d_in[4];
    const float* W1 = (const float*)d_in[5];
    const float* b1 = (const float*)d_in[6];
    const float* W2 = (const float*)d_in[7];
    const float* b2 = (const float*)d_in[8];
    float* out = (float*)d_out;

    float* pq  = sym(nullptr, (const void*)g_q);
    float* pk  = sym(nullptr, (const void*)g_k);
    float* pv  = sym(nullptr, (const void*)g_v);
    float* ps  = sym(nullptr, (const void*)g_s);
    float* pt1 = sym(nullptr, (const void*)g_t1);
    float* pao = sym(nullptr, (const void*)g_ao);
    float* py  = sym(nullptr, (const void*)g_y);
    float* ph1 = sym(nullptr, (const void*)g_h1);
    float* ph2 = sym(nullptr, (const void*)g_h2);

    const long long sXD = (long long)DD * SS;   // x batch stride
    const long long sSD = (long long)SS * DD;   // [S,D] batch stride
    const long long sSS = (long long)SS * SS;   // scores batch stride
    const long long sSF = (long long)SS * FF;

    zero_acc_kernel<<<1, 32>>>();

    dim3 blk(256);
    dim3 gNarrow(DD / TN, SS / TM, BB);     // N=512  -> (4,32,8)
    dim3 gScore(SS / TN, SS / TM, BB);      // N=4096 -> (32,32,8)
    dim3 gFFN(FF / TN, SS / TM, BB);        // N=2048 -> (16,32,8)

    // q,k,v = x^T @ W   (A K-major: x[b] is [D,S]; W is [D,D] K-major)
    gemm_kernel<true,  true,  0><<<gNarrow, blk>>>(x, Wq, nullptr, pq,
        SS, DD, DD, SS, DD, DD, sXD, 0, sSD);
    gemm_kernel<true,  true,  0><<<gNarrow, blk>>>(x, Wk, nullptr, pk,
        SS, DD, DD, SS, DD, DD, sXD, 0, sSD);
    gemm_kernel<true,  true,  0><<<gNarrow, blk>>>(x, Wv, nullptr, pv,
        SS, DD, DD, SS, DD, DD, sXD, 0, sSD);

    // scores = q @ k^T  (both [S,D] row major -> NT)
    gemm_kernel<false, false, 0><<<gScore, blk>>>(pq, pk, nullptr, ps,
        SS, SS, DD, DD, DD, SS, sSD, sSD, sSS);

    // softmax (scale folded in)
    softmax_kernel<<<BB * SS, 256>>>(ps, 0.04419417382415922f /* 1/sqrt(512) */);

    // t1 = attn @ v     (NN)
    gemm_kernel<false, true,  0><<<gNarrow, blk>>>(ps, pv, nullptr, pt1,
        SS, DD, SS, SS, DD, DD, sSS, sSD, sSD);

    // ao = t1 @ Wo      (NN, shared weight)
    gemm_kernel<false, true,  0><<<gNarrow, blk>>>(pt1, Wo, nullptr, pao,
        SS, DD, DD, DD, DD, DD, sSD, 0, sSD);

    // residual 1 + stats; then normalize (post stored in g_y, [B,S,D])
    dim3 rblk(32, 8);
    dim3 rgrid(SS / 32, DD / 32, BB);       // (128,16,8)
    resid1_kernel<<<rgrid, rblk>>>(x, pao, py);
    apply1_kernel<<<dim3(2048, BB), 256>>>(py);

    // FFN
    gemm_kernel<false, true,  2><<<gFFN, blk>>>(py, W1, b1, ph1,
        SS, FF, DD, DD, FF, FF, sSD, 0, sSF);
    gemm_kernel<false, true,  1><<<gNarrow, blk>>>(ph1, W2, b2, ph2,
        SS, DD, FF, FF, DD, DD, sSF, 0, sSD);

    // residual 2 + stats; normalize + transpose to [B,D,S] output
    resid2_kernel<<<dim3(2048, BB), 256>>>(py, ph2);
    apply2t_kernel<<<rgrid, rblk>>>(ph2, out);

    (void)in_sizes; (void)n_in; (void)out_size;
}

// round 2
// speedup vs baseline: 1.0002x; 1.0002x over previous
#include <cuda_runtime.h>
#include <cuda_bf16.h>
#include <math.h>

// Problem constants
#define BB 8
#define DD 512
#define SS 4096
#define FF 2048

// ---------------- static scratch (no allocations allowed) ----------------
__device__ float g_q [(size_t)BB * SS * DD];          // 64MB  [B,S,D]
__device__ float g_k [(size_t)BB * SS * DD];          // 64MB
__device__ float g_v [(size_t)BB * SS * DD];          // 64MB
__device__ float g_s [(size_t)BB * SS * SS];          // 512MB [B,S,S] scores/attn
__device__ float g_t1[(size_t)BB * SS * DD];          // 64MB  attn@v
__device__ float g_ao[(size_t)BB * SS * DD];          // 64MB  (attn@v)@Wo
__device__ float g_y [(size_t)BB * SS * DD];          // 64MB  residual1 / post (normed in place)
__device__ float g_h1[(size_t)BB * SS * FF];          // 256MB FFN hidden
__device__ float g_h2[(size_t)BB * SS * DD];          // 64MB  FFN out -> residual2 in place
__device__ double g_acc[32];                          // [stage(2)][batch(8)][sum,sumsq]

// ---------------- GEMM: C = A*B (+bias, +relu), batched ----------------
// AK: A stored K-major [K,M] (lda = row stride). else [M,K].
// BK: B stored K-major [K,N]. else [N,K].
// EPI: 0 none, 1 +bias, 2 relu(+bias)
#define TM 128
#define TN 128
#define TK 16

template <bool AK, bool BK, int EPI>
__global__ __launch_bounds__(256, 2)
void gemm_kernel(const float* __restrict__ A, const float* __restrict__ B,
                 const float* __restrict__ bias, float* __restrict__ C,
                 int M, int N, int K, int lda, int ldb, int ldc,
                 long long sA, long long sB, long long sC)
{
    __shared__ float As[TK][TM];
    __shared__ float Bs[TK][TN];

    const int bz = blockIdx.z;
    A += (long long)bz * sA;
    B += (long long)bz * sB;
    C += (long long)bz * sC;

    const int m0 = blockIdx.y * TM;
    const int n0 = blockIdx.x * TN;
    const int tid = threadIdx.x;
    const int r = tid >> 4;   // 0..15
    const int c = tid & 15;   // 0..15

    float acc[8][8];
#pragma unroll
    for (int i = 0; i < 8; i++)
#pragma unroll
        for (int j = 0; j < 8; j++) acc[i][j] = 0.f;

    for (int k0 = 0; k0 < K; k0 += TK) {
        // ---- load A tile ----
#pragma unroll
        for (int it = 0; it < 2; it++) {
            int idx = tid + it * 256;      // 0..511 float4 slots (2048 floats)
            if (AK) {
                int kk = idx >> 5;         // 0..15
                int mq = idx & 31;         // 0..31 (float4 across M)
                float4 va = *(const float4*)(A + (long long)(k0 + kk) * lda + m0 + mq * 4);
                *(float4*)(&As[kk][mq * 4]) = va;
            } else {
                int m  = idx >> 2;         // 0..127
                int kq = idx & 3;          // float4 across K
                float4 va = *(const float4*)(A + (long long)(m0 + m) * lda + k0 + kq * 4);
                As[kq * 4 + 0][m] = va.x;
                As[kq * 4 + 1][m] = va.y;
                As[kq * 4 + 2][m] = va.z;
                As[kq * 4 + 3][m] = va.w;
            }
        }
        // ---- load B tile ----
#pragma unroll
        for (int it = 0; it < 2; it++) {
            int idx = tid + it * 256;
            if (BK) {
                int kk = idx >> 5;
                int nq = idx & 31;
                float4 vb = *(const float4*)(B + (long long)(k0 + kk) * ldb + n0 + nq * 4);
                *(float4*)(&Bs[kk][nq * 4]) = vb;
            } else {
                int n  = idx >> 2;
                int kq = idx & 3;
                float4 vb = *(const float4*)(B + (long long)(n0 + n) * ldb + k0 + kq * 4);
                Bs[kq * 4 + 0][n] = vb.x;
                Bs[kq * 4 + 1][n] = vb.y;
                Bs[kq * 4 + 2][n] = vb.z;
                Bs[kq * 4 + 3][n] = vb.w;
            }
        }
        __syncthreads();

#pragma unroll
        for (int kk = 0; kk < TK; kk++) {
            float a[8], bv[8];
#pragma unroll
            for (int i = 0; i < 8; i++) a[i]  = As[kk][r * 8 + i];
#pragma unroll
            for (int j = 0; j < 8; j++) bv[j] = Bs[kk][c * 8 + j];
#pragma unroll
            for (int i = 0; i < 8; i++)
#pragma unroll
                for (int j = 0; j < 8; j++)
                    acc[i][j] = fmaf(a[i], bv[j], acc[i][j]);
        }
        __syncthreads();
    }

    // ---- epilogue ----
#pragma unroll
    for (int i = 0; i < 8; i++) {
        int m = m0 + r * 8 + i;
#pragma unroll
        for (int j = 0; j < 8; j += 4) {
            int n = n0 + c * 8 + j;
            float4 o;
            o.x = acc[i][j + 0];
            o.y = acc[i][j + 1];
            o.z = acc[i][j + 2];
            o.w = acc[i][j + 3];
            if (EPI >= 1) {
                o.x += bias[n + 0]; o.y += bias[n + 1];
                o.z += bias[n + 2]; o.w += bias[n + 3];
            }
            if (EPI == 2) {
                o.x = fmaxf(o.x, 0.f); o.y = fmaxf(o.y, 0.f);
                o.z = fmaxf(o.z, 0.f); o.w = fmaxf(o.w, 0.f);
            }
            *(float4*)(C + (long long)m * ldc + n) = o;
        }
    }
}

// ---------------- softmax over rows of g_s (in place, scaled) ----------------
__global__ void softmax_kernel(float* __restrict__ s, float scale)
{
    const long long row = blockIdx.x;                 // 0 .. B*S-1
    float4* p = (float4*)(s + row * SS);              // 1024 float4 per row
    const int tid = threadIdx.x;                      // 256 threads
    __shared__ float red[256];

    float4 v[4];
    float mx = -INFINITY;
#pragma unroll
    for (int ii = 0; ii < 4; ii++) {
        v[ii] = p[tid + ii * 256];
        mx = fmaxf(mx, fmaxf(fmaxf(v[ii].x, v[ii].y), fmaxf(v[ii].z, v[ii].w)));
    }
    red[tid] = mx; __syncthreads();
    for (int o = 128; o > 0; o >>= 1) {
        if (tid < o) red[tid] = fmaxf(red[tid], red[tid + o]);
        __syncthreads();
    }
    mx = red[0];
    __syncthreads();

    float sum = 0.f;
#pragma unroll
    for (int ii = 0; ii < 4; ii++) {
        v[ii].x = __expf((v[ii].x - mx) * scale);
        v[ii].y = __expf((v[ii].y - mx) * scale);
        v[ii].z = __expf((v[ii].z - mx) * scale);
        v[ii].w = __expf((v[ii].w - mx) * scale);
        sum += v[ii].x + v[ii].y + v[ii].z + v[ii].w;
    }
    red[tid] = sum; __syncthreads();
    for (int o = 128; o > 0; o >>= 1) {
        if (tid < o) red[tid] += red[tid + o];
        __syncthreads();
    }
    const float inv = 1.f / red[0];
#pragma unroll
    for (int ii = 0; ii < 4; ii++) {
        v[ii].x *= inv; v[ii].y *= inv; v[ii].z *= inv; v[ii].w *= inv;
        p[tid + ii * 256] = v[ii];
    }
}

// ---------------- reductions for the global norm ----------------
__device__ __forceinline__ void block_reduce_add2(float a, float b, int t, double* dst)
{
    __shared__ float sa[256], sb[256];
    sa[t] = a; sb[t] = b; __syncthreads();
    for (int o = 128; o > 0; o >>= 1) {
        if (t < o) { sa[t] += sa[t + o]; sb[t] += sb[t + o]; }
        __syncthreads();
    }
    if (t == 0) {
        atomicAdd(dst + 0, (double)sa[0]);
        atomicAdd(dst + 1, (double)sb[0]);
    }
}

__global__ void zero_acc_kernel()
{
    if (threadIdx.x < 32) g_acc[threadIdx.x] = 0.0;
}

// y[b,s,d] = x[b,d,s] + ao[b,s,d]; accumulate sum & sumsq per batch (stage 0)
__global__ void resid1_kernel(const float* __restrict__ x, const float* __restrict__ ao,
                              float* __restrict__ y)
{
    const int b  = blockIdx.z;
    const int s0 = blockIdx.x * 32;
    const int d0 = blockIdx.y * 32;
    __shared__ float xs[32][33];
    const int tx = threadIdx.x, ty = threadIdx.y;   // 32 x 8
    const int t = ty * 32 + tx;

    const float* xb = x + (long long)b * DD * SS;
#pragma unroll
    for (int i = 0; i < 32; i += 8)
        xs[ty + i][tx] = xb[(long long)(d0 + ty + i) * SS + s0 + tx];
    __syncthreads();

    float ls = 0.f, lq = 0.f;
#pragma unroll
    for (int i = 0; i < 32; i += 8) {
        long long off = ((long long)b * SS + s0 + ty + i) * DD + d0 + tx;
        float vv = ao[off] + xs[tx][ty + i];
        y[off] = vv;
        ls += vv;
        lq += vv * vv;
    }
    block_reduce_add2(ls, lq, t, g_acc + 2 * b);
}

// normalize y in place with stage-0 stats
__global__ void apply1_kernel(float* __restrict__ y)
{
    const int b = blockIdx.y;
    const double sum = g_acc[2 * b], sq = g_acc[2 * b + 1];
    const double NE = (double)SS * DD;
    const double mean = sum / NE;
    double var = sq - NE * mean * mean;
    if (var < 0.0) var = 0.0;
    const float inv = (float)(1.0 / (sqrt(var) + 1e-7));
    const float fm = (float)mean;

    float4* y4 = ((float4*)y) + (long long)b * (SS * DD / 4);
    const long long i = (long long)blockIdx.x * 256 + threadIdx.x;  // grid.x = 2048 exact
    float4 vv = y4[i];
    vv.x = (vv.x - fm) * inv; vv.y = (vv.y - fm) * inv;
    vv.z = (vv.z - fm) * inv; vv.w = (vv.w - fm) * inv;
    y4[i] = vv;
}

// h2 <- post + h2 ; accumulate stats (stage 1)
__global__ void resid2_kernel(const float* __restrict__ post, float* __restrict__ h2)
{
    const int b = blockIdx.y;
    const float4* p4 = ((const float4*)post) + (long long)b * (SS * DD / 4);
    float4*       h4 = ((float4*)h2)   + (long long)b * (SS * DD / 4);
    const long long i = (long long)blockIdx.x * 256 + threadIdx.x;
    float4 a = p4[i], cc = h4[i];
    a.x += cc.x; a.y += cc.y; a.z += cc.z; a.w += cc.w;
    h4[i] = a;
    float ls = a.x + a.y + a.z + a.w;
    float lq = a.x * a.x + a.y * a.y + a.z * a.z + a.w * a.w;
    block_reduce_add2(ls, lq, threadIdx.x, g_acc + 16 + 2 * b);
}

// out[b,d,s] = (y2[b,s,d] - mean) * inv   (stage-1 stats), transposed write
__global__ void apply2t_kernel(const float* __restrict__ y2, float* __restrict__ out)
{
    const int b = blockIdx.z;
    const double sum = g_acc[16 + 2 * b], sq = g_acc[16 + 2 * b + 1];
    const double NE = (double)SS * DD;
    const double mean = sum / NE;
    double var = sq - NE * mean * mean;
    if (var < 0.0) var = 0.0;
    const float inv = (float)(1.0 / (sqrt(var) + 1e-7));
    const float fm = (float)mean;

    const int s0 = blockIdx.x * 32;
    const int d0 = blockIdx.y * 32;
    __shared__ float ys[32][33];
    const int tx = threadIdx.x, ty = threadIdx.y;   // 32 x 8

#pragma unroll
    for (int i = 0; i < 32; i += 8)
        ys[ty + i][tx] = y2[((long long)b * SS + s0 + ty + i) * DD + d0 + tx];
    __syncthreads();
#pragma unroll
    for (int i = 0; i < 32; i += 8)
        out[((long long)b * DD + d0 + ty + i) * SS + s0 + tx] =
            (ys[tx][ty + i] - fm) * inv;
}

// ---------------- host-side orchestration ----------------
static float* sym(float* /*dummy*/, const void* symbol)
{
    void* p = nullptr;
    cudaGetSymbolAddress(&p, symbol);
    return (float*)p;
}

extern "C" void kernel_launch(void* const* d_in, const int* in_sizes, int n_in,
                              void* d_out, int out_size)
{
    const float* x  = (const float*)d_in[0];
    const float* Wq = (const float*)d_in[1];
    const float* Wk = (const float*)d_in[2];
    const float* Wv = (const float*)d_in[3];
    const float* Wo = (const float*)d_in[4];
    const float* W1 = (const float*)d_in[5];
    const float* b1 = (const float*)d_in[6];
    const float* W2 = (const float*)d_in[7];
    const float* b2 = (const float*)d_in[8];
    float* out = (float*)d_out;

    float* pq  = sym(nullptr, (const void*)g_q);
    float* pk  = sym(nullptr, (const void*)g_k);
    float* pv  = sym(nullptr, (const void*)g_v);
    float* ps  = sym(nullptr, (const void*)g_s);
    float* pt1 = sym(nullptr, (const void*)g_t1);
    float* pao = sym(nullptr, (const void*)g_ao);
    float* py  = sym(nullptr, (const void*)g_y);
    float* ph1 = sym(nullptr, (const void*)g_h1);
    float* ph2 = sym(nullptr, (const void*)g_h2);

    const long long sXD = (long long)DD * SS;   // x batch stride
    const long long sSD = (long long)SS * DD;   // [S,D] batch stride
    const long long sSS = (long long)SS * SS;   // scores batch stride
    const long long sSF = (long long)SS * FF;

    zero_acc_kernel<<<1, 32>>>();

    dim3 blk(256);
    dim3 gNarrow(DD / TN, SS / TM, BB);     // N=512  -> (4,32,8)
    dim3 gScore(SS / TN, SS / TM, BB);      // N=4096 -> (32,32,8)
    dim3 gFFN(FF / TN, SS / TM, BB);        // N=2048 -> (16,32,8)

    // q,k,v = x^T @ W   (A K-major: x[b] is [D,S]; W is [D,D] K-major)
    gemm_kernel<true,  true,  0><<<gNarrow, blk>>>(x, Wq, nullptr, pq,
        SS, DD, DD, SS, DD, DD, sXD, 0, sSD);
    gemm_kernel<true,  true,  0><<<gNarrow, blk>>>(x, Wk, nullptr, pk,
        SS, DD, DD, SS, DD, DD, sXD, 0, sSD);
    gemm_kernel<true,  true,  0><<<gNarrow, blk>>>(x, Wv, nullptr, pv,
        SS, DD, DD, SS, DD, DD, sXD, 0, sSD);

    // scores = q @ k^T  (both [S,D] row major -> NT)
    gemm_kernel<false, false, 0><<<gScore, blk>>>(pq, pk, nullptr, ps,
        SS, SS, DD, DD, DD, SS, sSD, sSD, sSS);

    // softmax (scale folded in)
    softmax_kernel<<<BB * SS, 256>>>(ps, 0.04419417382415922f /* 1/sqrt(512) */);

    // t1 = attn @ v     (NN)
    gemm_kernel<false, true,  0><<<gNarrow, blk>>>(ps, pv, nullptr, pt1,
        SS, DD, SS, SS, DD, DD, sSS, sSD, sSD);

    // ao = t1 @ Wo      (NN, shared weight)
    gemm_kernel<false, true,  0><<<gNarrow, blk>>>(pt1, Wo, nullptr, pao,
        SS, DD, DD, DD, DD, DD, sSD, 0, sSD);

    // residual 1 + stats; then normalize (post stored in g_y, [B,S,D])
    dim3 rblk(32, 8);
    dim3 rgrid(SS / 32, DD / 32, BB);       // (128,16,8)
    resid1_kernel<<<rgrid, rblk>>>(x, pao, py);
    apply1_kernel<<<dim3(2048, BB), 256>>>(py);

    // FFN
    gemm_kernel<false, true,  2><<<gFFN, blk>>>(py, W1, b1, ph1,
        SS, FF, DD, DD, FF, FF, sSD, 0, sSF);
    gemm_kernel<false, true,  1><<<gNarrow, blk>>>(ph1, W2, b2, ph2,
        SS, DD, FF, FF, DD, DD, sSF, 0, sSD);

    // residual 2 + stats; normalize + transpose to [B,D,S] output
    resid2_kernel<<<dim3(2048, BB), 256>>>(py, ph2);
    apply2t_kernel<<<rgrid, rblk>>>(ph2, out);

    (void)in_sizes; (void)n_in; (void)out_size;
}

// round 3
// speedup vs baseline: 2.7709x; 2.7704x over previous
#include <cuda_runtime.h>
#include <cuda_bf16.h>
#include <math.h>
#include <stdint.h>

// Problem constants
#define BB 8
#define DD 512
#define SS 4096
#define FF 2048

// ---------------- static scratch (no allocations allowed) ----------------
__device__ float g_q [(size_t)BB * SS * DD];
__device__ float g_k [(size_t)BB * SS * DD];
__device__ float g_v [(size_t)BB * SS * DD];
__device__ float g_s [(size_t)BB * SS * SS];
__device__ float g_t1[(size_t)BB * SS * DD];
__device__ float g_ao[(size_t)BB * SS * DD];
__device__ float g_y [(size_t)BB * SS * DD];
__device__ float g_h1[(size_t)BB * SS * FF];
__device__ float g_h2[(size_t)BB * SS * DD];
__device__ double g_acc[32];

// ---------------- tf32 tensor-core GEMM ----------------
// C[M,N] = A*B (+bias, +relu). Batched over blockIdx.z.
// AK: A stored K-major [K,M] in gmem. else [M,K].
// BK: B stored K-major [K,N]. else [N,K].
#define TM 128
#define TN 128
#define TK 32
#define S1 136   // smem stride for [k][x] layout (bank = 8k+x, conflict-free)
#define S2 36    // smem stride for [x][k] layout (bank = 4x+k, conflict-free)

__device__ __forceinline__ uint32_t f2tf32(float f)
{
    uint32_t o;
    asm("cvt.rna.tf32.f32 %0, %1;" : "=r"(o) : "f"(f));
    return o;
}

__device__ __forceinline__ void mma_tf32(float c[4], const uint32_t a[4], const uint32_t b[2])
{
    asm volatile(
        "mma.sync.aligned.m16n8k8.row.col.f32.tf32.tf32.f32 "
        "{%0,%1,%2,%3}, {%4,%5,%6,%7}, {%8,%9}, {%0,%1,%2,%3};\n"
        : "+f"(c[0]), "+f"(c[1]), "+f"(c[2]), "+f"(c[3])
        : "r"(a[0]), "r"(a[1]), "r"(a[2]), "r"(a[3]),
          "r"(b[0]), "r"(b[1]));
}

template <bool AK, bool BK, int EPI>
__global__ __launch_bounds__(256, 2)
void gemm_kernel(const float* __restrict__ A, const float* __restrict__ B,
                 const float* __restrict__ bias, float* __restrict__ C,
                 int M, int N, int K, int lda, int ldb, int ldc,
                 long long sA, long long sB, long long sC)
{
    // layout1 [k][x]: TK*S1 = 32*136 = 4352 floats
    // layout2 [x][k]: 128*S2 = 128*36 = 4608 floats
    __shared__ __align__(16) float sAm[AK ? TK * S1 : TM * S2];
    __shared__ __align__(16) float sBm[BK ? TK * S1 : TN * S2];

    const int bz = blockIdx.z;
    A += (long long)bz * sA;
    B += (long long)bz * sB;
    C += (long long)bz * sC;

    const int m0 = blockIdx.y * TM;
    const int n0 = blockIdx.x * TN;
    const int tid  = threadIdx.x;
    const int lane = tid & 31;
    const int warp = tid >> 5;
    const int wm = (warp >> 2) * 64;   // warp M offset: 0 / 64
    const int wn = (warp & 3)  * 32;   // warp N offset: 0/32/64/96
    const int qr = lane >> 2;          // 0..7
    const int qc = lane & 3;           // 0..3

    float acc[4][4][4];
#pragma unroll
    for (int i = 0; i < 4; i++)
#pragma unroll
        for (int j = 0; j < 4; j++)
#pragma unroll
            for (int q = 0; q < 4; q++) acc[i][j][q] = 0.f;

    for (int k0 = 0; k0 < K; k0 += TK) {
        // ---- stage A tile (convert to tf32) ----
#pragma unroll
        for (int it = 0; it < 4; it++) {
            int idx = tid + it * 256;                 // 0..1023 float4 slots
            if (AK) {
                int kk = idx >> 5, mq = idx & 31;
                float4 v = *(const float4*)(A + (long long)(k0 + kk) * lda + m0 + mq * 4);
                uint32_t* d = (uint32_t*)(sAm + kk * S1 + mq * 4);
                d[0] = f2tf32(v.x); d[1] = f2tf32(v.y);
                d[2] = f2tf32(v.z); d[3] = f2tf32(v.w);
            } else {
                int m = idx >> 3, kq = idx & 7;       // TK/4 = 8 float4 per row
                float4 v = *(const float4*)(A + (long long)(m0 + m) * lda + k0 + kq * 4);
                uint32_t* d = (uint32_t*)(sAm + m * S2 + kq * 4);
                d[0] = f2tf32(v.x); d[1] = f2tf32(v.y);
                d[2] = f2tf32(v.z); d[3] = f2tf32(v.w);
            }
        }
        // ---- stage B tile ----
#pragma unroll
        for (int it = 0; it < 4; it++) {
            int idx = tid + it * 256;
            if (BK) {
                int kk = idx >> 5, nq = idx & 31;
                float4 v = *(const float4*)(B + (long long)(k0 + kk) * ldb + n0 + nq * 4);
                uint32_t* d = (uint32_t*)(sBm + kk * S1 + nq * 4);
                d[0] = f2tf32(v.x); d[1] = f2tf32(v.y);
                d[2] = f2tf32(v.z); d[3] = f2tf32(v.w);
            } else {
                int n = idx >> 3, kq = idx & 7;
                float4 v = *(const float4*)(B + (long long)(n0 + n) * ldb + k0 + kq * 4);
                uint32_t* d = (uint32_t*)(sBm + n * S2 + kq * 4);
                d[0] = f2tf32(v.x); d[1] = f2tf32(v.y);
                d[2] = f2tf32(v.z); d[3] = f2tf32(v.w);
            }
        }
        __syncthreads();

        // ---- 4 k-steps of m16n8k8 ----
#pragma unroll
        for (int ks = 0; ks < TK / 8; ks++) {
            const int kb = ks * 8;
            uint32_t af[4][4];
#pragma unroll
            for (int mi = 0; mi < 4; mi++) {
                const int mrow = wm + mi * 16 + qr;
                if (AK) {
                    const uint32_t* p = (const uint32_t*)(sAm + (kb + qc) * S1 + mrow);
                    af[mi][0] = p[0];
                    af[mi][1] = p[8];
                    af[mi][2] = p[4 * S1];
                    af[mi][3] = p[4 * S1 + 8];
                } else {
                    const uint32_t* p = (const uint32_t*)(sAm + mrow * S2 + kb + qc);
                    af[mi][0] = p[0];
                    af[mi][1] = p[8 * S2];
                    af[mi][2] = p[4];
                    af[mi][3] = p[8 * S2 + 4];
                }
            }
            uint32_t bf[4][2];
#pragma unroll
            for (int ni = 0; ni < 4; ni++) {
                const int ncol = wn + ni * 8 + qr;
                if (BK) {
                    const uint32_t* p = (const uint32_t*)(sBm + (kb + qc) * S1 + ncol);
                    bf[ni][0] = p[0];
                    bf[ni][1] = p[4 * S1];
                } else {
                    const uint32_t* p = (const uint32_t*)(sBm + ncol * S2 + kb + qc);
                    bf[ni][0] = p[0];
                    bf[ni][1] = p[4];
                }
            }
#pragma unroll
            for (int mi = 0; mi < 4; mi++)
#pragma unroll
                for (int ni = 0; ni < 4; ni++)
                    mma_tf32(acc[mi][ni], af[mi], bf[ni]);
        }
        __syncthreads();
    }

    // ---- epilogue ----
#pragma unroll
    for (int mi = 0; mi < 4; mi++) {
        const int mr = m0 + wm + mi * 16 + qr;
#pragma unroll
        for (int ni = 0; ni < 4; ni++) {
            const int nc = n0 + wn + ni * 8 + 2 * qc;
            float2 lo, hi;
            lo.x = acc[mi][ni][0]; lo.y = acc[mi][ni][1];
            hi.x = acc[mi][ni][2]; hi.y = acc[mi][ni][3];
            if (EPI >= 1) {
                float bx = bias[nc], by = bias[nc + 1];
                lo.x += bx; lo.y += by; hi.x += bx; hi.y += by;
            }
            if (EPI == 2) {
                lo.x = fmaxf(lo.x, 0.f); lo.y = fmaxf(lo.y, 0.f);
                hi.x = fmaxf(hi.x, 0.f); hi.y = fmaxf(hi.y, 0.f);
            }
            *(float2*)(C + (long long)mr * ldc + nc) = lo;
            *(float2*)(C + (long long)(mr + 8) * ldc + nc) = hi;
        }
    }
}

// ---------------- softmax over rows of g_s (in place, scaled) ----------------
__global__ void softmax_kernel(float* __restrict__ s, float scale)
{
    const long long row = blockIdx.x;
    float4* p = (float4*)(s + row * SS);
    const int tid = threadIdx.x;
    __shared__ float red[256];

    float4 v[4];
    float mx = -INFINITY;
#pragma unroll
    for (int ii = 0; ii < 4; ii++) {
        v[ii] = p[tid + ii * 256];
        mx = fmaxf(mx, fmaxf(fmaxf(v[ii].x, v[ii].y), fmaxf(v[ii].z, v[ii].w)));
    }
    red[tid] = mx; __syncthreads();
    for (int o = 128; o > 0; o >>= 1) {
        if (tid < o) red[tid] = fmaxf(red[tid], red[tid + o]);
        __syncthreads();
    }
    mx = red[0];
    __syncthreads();

    float sum = 0.f;
#pragma unroll
    for (int ii = 0; ii < 4; ii++) {
        v[ii].x = __expf((v[ii].x - mx) * scale);
        v[ii].y = __expf((v[ii].y - mx) * scale);
        v[ii].z = __expf((v[ii].z - mx) * scale);
        v[ii].w = __expf((v[ii].w - mx) * scale);
        sum += v[ii].x + v[ii].y + v[ii].z + v[ii].w;
    }
    red[tid] = sum; __syncthreads();
    for (int o = 128; o > 0; o >>= 1) {
        if (tid < o) red[tid] += red[tid + o];
        __syncthreads();
    }
    const float inv = 1.f / red[0];
#pragma unroll
    for (int ii = 0; ii < 4; ii++) {
        v[ii].x *= inv; v[ii].y *= inv; v[ii].z *= inv; v[ii].w *= inv;
        p[tid + ii * 256] = v[ii];
    }
}

// ---------------- reductions for the global norm ----------------
__device__ __forceinline__ void block_reduce_add2(float a, float b, int t, double* dst)
{
    __shared__ float sa[256], sb[256];
    sa[t] = a; sb[t] = b; __syncthreads();
    for (int o = 128; o > 0; o >>= 1) {
        if (t < o) { sa[t] += sa[t + o]; sb[t] += sb[t + o]; }
        __syncthreads();
    }
    if (t == 0) {
        atomicAdd(dst + 0, (double)sa[0]);
        atomicAdd(dst + 1, (double)sb[0]);
    }
}

__global__ void zero_acc_kernel()
{
    if (threadIdx.x < 32) g_acc[threadIdx.x] = 0.0;
}

__global__ void resid1_kernel(const float* __restrict__ x, const float* __restrict__ ao,
                              float* __restrict__ y)
{
    const int b  = blockIdx.z;
    const int s0 = blockIdx.x * 32;
    const int d0 = blockIdx.y * 32;
    __shared__ float xs[32][33];
    const int tx = threadIdx.x, ty = threadIdx.y;
    const int t = ty * 32 + tx;

    const float* xb = x + (long long)b * DD * SS;
#pragma unroll
    for (int i = 0; i < 32; i += 8)
        xs[ty + i][tx] = xb[(long long)(d0 + ty + i) * SS + s0 + tx];
    __syncthreads();

    float ls = 0.f, lq = 0.f;
#pragma unroll
    for (int i = 0; i < 32; i += 8) {
        long long off = ((long long)b * SS + s0 + ty + i) * DD + d0 + tx;
        float vv = ao[off] + xs[tx][ty + i];
        y[off] = vv;
        ls += vv;
        lq += vv * vv;
    }
    block_reduce_add2(ls, lq, t, g_acc + 2 * b);
}

__global__ void apply1_kernel(float* __restrict__ y)
{
    const int b = blockIdx.y;
    const double sum = g_acc[2 * b], sq = g_acc[2 * b + 1];
    const double NE = (double)SS * DD;
    const double mean = sum / NE;
    double var = sq - NE * mean * mean;
    if (var < 0.0) var = 0.0;
    const float inv = (float)(1.0 / (sqrt(var) + 1e-7));
    const float fm = (float)mean;

    float4* y4 = ((float4*)y) + (long long)b * (SS * DD / 4);
    const long long i = (long long)blockIdx.x * 256 + threadIdx.x;
    float4 vv = y4[i];
    vv.x = (vv.x - fm) * inv; vv.y = (vv.y - fm) * inv;
    vv.z = (vv.z - fm) * inv; vv.w = (vv.w - fm) * inv;
    y4[i] = vv;
}

__global__ void resid2_kernel(const float* __restrict__ post, float* __restrict__ h2)
{
    const int b = blockIdx.y;
    const float4* p4 = ((const float4*)post) + (long long)b * (SS * DD / 4);
    float4*       h4 = ((float4*)h2)   + (long long)b * (SS * DD / 4);
    const long long i = (long long)blockIdx.x * 256 + threadIdx.x;
    float4 a = p4[i], cc = h4[i];
    a.x += cc.x; a.y += cc.y; a.z += cc.z; a.w += cc.w;
    h4[i] = a;
    float ls = a.x + a.y + a.z + a.w;
    float lq = a.x * a.x + a.y * a.y + a.z * a.z + a.w * a.w;
    block_reduce_add2(ls, lq, threadIdx.x, g_acc + 16 + 2 * b);
}

__global__ void apply2t_kernel(const float* __restrict__ y2, float* __restrict__ out)
{
    const int b = blockIdx.z;
    const double sum = g_acc[16 + 2 * b], sq = g_acc[16 + 2 * b + 1];
    const double NE = (double)SS * DD;
    const double mean = sum / NE;
    double var = sq - NE * mean * mean;
    if (var < 0.0) var = 0.0;
    const float inv = (float)(1.0 / (sqrt(var) + 1e-7));
    const float fm = (float)mean;

    const int s0 = blockIdx.x * 32;
    const int d0 = blockIdx.y * 32;
    __shared__ float ys[32][33];
    const int tx = threadIdx.x, ty = threadIdx.y;

#pragma unroll
    for (int i = 0; i < 32; i += 8)
        ys[ty + i][tx] = y2[((long long)b * SS + s0 + ty + i) * DD + d0 + tx];
    __syncthreads();
#pragma unroll
    for (int i = 0; i < 32; i += 8)
        out[((long long)b * DD + d0 + ty + i) * SS + s0 + tx] =
            (ys[tx][ty + i] - fm) * inv;
}

// ---------------- host-side orchestration ----------------
static float* sym(const void* symbol)
{
    void* p = nullptr;
    cudaGetSymbolAddress(&p, symbol);
    return (float*)p;
}

extern "C" void kernel_launch(void* const* d_in, const int* in_sizes, int n_in,
                              void* d_out, int out_size)
{
    const float* x  = (const float*)d_in[0];
    const float* Wq = (const float*)d_in[1];
    const float* Wk = (const float*)d_in[2];
    const float* Wv = (const float*)d_in[3];
    const float* Wo = (const float*)d_in[4];
    const float* W1 = (const float*)d_in[5];
    const float* b1 = (const float*)d_in[6];
    const float* W2 = (const float*)d_in[7];
    const float* b2 = (const float*)d_in[8];
    float* out = (float*)d_out;

    float* pq  = sym((const void*)g_q);
    float* pk  = sym((const void*)g_k);
    float* pv  = sym((const void*)g_v);
    float* ps  = sym((const void*)g_s);
    float* pt1 = sym((const void*)g_t1);
    float* pao = sym((const void*)g_ao);
    float* py  = sym((const void*)g_y);
    float* ph1 = sym((const void*)g_h1);
    float* ph2 = sym((const void*)g_h2);

    const long long sXD = (long long)DD * SS;
    const long long sSD = (long long)SS * DD;
    const long long sSS = (long long)SS * SS;
    const long long sSF = (long long)SS * FF;

    zero_acc_kernel<<<1, 32>>>();

    dim3 blk(256);
    dim3 gNarrow(DD / TN, SS / TM, BB);
    dim3 gScore(SS / TN, SS / TM, BB);
    dim3 gFFN(FF / TN, SS / TM, BB);

    // q,k,v = x^T @ W
    gemm_kernel<true,  true,  0><<<gNarrow, blk>>>(x, Wq, nullptr, pq,
        SS, DD, DD, SS, DD, DD, sXD, 0, sSD);
    gemm_kernel<true,  true,  0><<<gNarrow, blk>>>(x, Wk, nullptr, pk,
        SS, DD, DD, SS, DD, DD, sXD, 0, sSD);
    gemm_kernel<true,  true,  0><<<gNarrow, blk>>>(x, Wv, nullptr, pv,
        SS, DD, DD, SS, DD, DD, sXD, 0, sSD);

    // scores = q @ k^T
    gemm_kernel<false, false, 0><<<gScore, blk>>>(pq, pk, nullptr, ps,
        SS, SS, DD, DD, DD, SS, sSD, sSD, sSS);

    softmax_kernel<<<BB * SS, 256>>>(ps, 0.04419417382415922f);

    // t1 = attn @ v
    gemm_kernel<false, true,  0><<<gNarrow, blk>>>(ps, pv, nullptr, pt1,
        SS, DD, SS, SS, DD, DD, sSS, sSD, sSD);

    // ao = t1 @ Wo
    gemm_kernel<false, true,  0><<<gNarrow, blk>>>(pt1, Wo, nullptr, pao,
        SS, DD, DD, DD, DD, DD, sSD, 0, sSD);

    dim3 rblk(32, 8);
    dim3 rgrid(SS / 32, DD / 32, BB);
    resid1_kernel<<<rgrid, rblk>>>(x, pao, py);
    apply1_kernel<<<dim3(2048, BB), 256>>>(py);

    // FFN
    gemm_kernel<false, true,  2><<<gFFN, blk>>>(py, W1, b1, ph1,
        SS, FF, DD, DD, FF, FF, sSD, 0, sSF);
    gemm_kernel<false, true,  1><<<gNarrow, blk>>>(ph1, W2, b2, ph2,
        SS, DD, FF, FF, DD, DD, sSF, 0, sSD);

    resid2_kernel<<<dim3(2048, BB), 256>>>(py, ph2);
    apply2t_kernel<<<rgrid, rblk>>>(ph2, out);

    (void)in_sizes; (void)n_in; (void)out_size;
}

// round 5
// speedup vs baseline: 5.1211x; 1.8482x over previous
#include <cuda_runtime.h>
#include <cuda_fp16.h>
#include <math.h>
#include <stdint.h>

// Problem constants
#define BB 8
#define DD 512
#define SS 4096
#define FF 2048

// ---------------- static scratch (no allocations allowed) ----------------
// fp32
__device__ float g_s [(size_t)BB * SS * SS];   // scores fp32
__device__ float g_ao[(size_t)BB * SS * DD];
__device__ float g_y [(size_t)BB * SS * DD];
__device__ float g_h2[(size_t)BB * SS * DD];
__device__ double g_acc[32];
// fp16 operands (row-major [x][k] for every GEMM)
__device__ __half g_xh [(size_t)BB * SS * DD];   // x^T  [B,S,D]
__device__ __half g_qh [(size_t)BB * SS * DD];
__device__ __half g_kh [(size_t)BB * SS * DD];
__device__ __half g_vt [(size_t)BB * DD * SS];   // v^T  [B,D,S]
__device__ __half g_sh [(size_t)BB * SS * SS];   // attn fp16
__device__ __half g_t1h[(size_t)BB * SS * DD];
__device__ __half g_yh [(size_t)BB * SS * DD];   // normalized post, fp16 copy
__device__ __half g_h1h[(size_t)BB * SS * FF];
__device__ __half g_wqT[DD * DD];
__device__ __half g_wkT[DD * DD];
__device__ __half g_wvT[DD * DD];
__device__ __half g_woT[DD * DD];
__device__ __half g_w1T[(size_t)DD * FF];        // [F,D]
__device__ __half g_w2T[(size_t)DD * FF];        // [D,F]

// ---------------- helpers ----------------
__device__ __forceinline__ uint32_t smem_u32(const void* p)
{
    uint32_t a;
    asm("{ .reg .u64 t; cvta.to.shared.u64 t, %1; cvt.u32.u64 %0, t; }" : "=r"(a) : "l"(p));
    return a;
}

#define CP16(d, s) asm volatile("cp.async.ca.shared.global [%0], [%1], 16;" :: "r"(d), "l"(s))
#define CPC()  asm volatile("cp.async.commit_group;" ::: "memory")
#define CPW0() asm volatile("cp.async.wait_group 0;" ::: "memory")
#define CPW1() asm volatile("cp.async.wait_group 1;" ::: "memory")

__device__ __forceinline__ void mma16816(float c[4], const uint32_t a[4], const uint32_t b[2])
{
    asm volatile(
        "mma.sync.aligned.m16n8k16.row.col.f32.f16.f16.f32 "
        "{%0,%1,%2,%3}, {%4,%5,%6,%7}, {%8,%9}, {%0,%1,%2,%3};\n"
        : "+f"(c[0]), "+f"(c[1]), "+f"(c[2]), "+f"(c[3])
        : "r"(a[0]), "r"(a[1]), "r"(a[2]), "r"(a[3]),
          "r"(b[0]), "r"(b[1]));
}

// ---------------- fp16 tensor-core GEMM, cp.async double-buffered ----------------
// C[M,N] = A[M,K] * B[N,K]^T, A/B fp16 row-major. 128x128 tile, TK=64.
// EPI: 0 none, 1 +bias, 2 relu(+bias)
// OUT: 0 fp32 [M,N]; 1 fp16 [M,N]; 2 fp16 transposed [N,M] (ldc = leading dim of [N,M])
#define SKH 72                    // smem row stride in halves (144B)
#define TILE_B (128 * SKH * 2)    // 18432 bytes
#define SMEMB (4 * TILE_B)        // 73728 bytes

template <int EPI, int OUT>
__global__ __launch_bounds__(256)
void gemm_h(const __half* __restrict__ A, const __half* __restrict__ B,
            const float* __restrict__ bias, void* __restrict__ Cv,
            int K, int lda, int ldb, int ldc,
            long long sA, long long sB, long long sC)
{
    extern __shared__ char smem[];
    const uint32_t base = smem_u32(smem);

    const int bz = blockIdx.z;
    const __half* Ab = A + (long long)bz * sA;
    const __half* Bb = B + (long long)bz * sB;

    const int m0 = blockIdx.y * 128;
    const int n0 = blockIdx.x * 128;
    const int tid  = threadIdx.x;
    const int lane = tid & 31;
    const int warp = tid >> 5;
    const int wm = (warp >> 2) * 64;
    const int wn = (warp & 3) * 32;
    const int qr = lane >> 2;   // 0..7
    const int qc = lane & 3;    // 0..3

    float acc[4][4][4];
#pragma unroll
    for (int i = 0; i < 4; i++)
#pragma unroll
        for (int j = 0; j < 4; j++)
#pragma unroll
            for (int q = 0; q < 4; q++) acc[i][j][q] = 0.f;

    const int NKB = K >> 6;

    // staging: 1024 16B chunks per operand (128 rows x 8 chunks), 4 per thread
    const int sx = tid >> 3;        // row group base (0..31), +32 per iter
    const int sc = tid & 7;         // chunk in row
    const uint32_t sdst = (uint32_t)(sx * 144 + sc * 16);

#define STAGE(buf, k0)                                                          \
    do {                                                                        \
        const uint32_t aD = base + (buf) * TILE_B + sdst;                       \
        const uint32_t bD = base + (2 + (buf)) * TILE_B + sdst;                 \
        const __half* aSrc = Ab + (long long)(m0 + sx) * lda + (k0) + sc * 8;   \
        const __half* bSrc = Bb + (long long)(n0 + sx) * ldb + (k0) + sc * 8;   \
        _Pragma("unroll")                                                       \
        for (int it = 0; it < 4; it++) {                                        \
            CP16(aD + it * (32 * 144), aSrc + (long long)(it * 32) * lda);      \
            CP16(bD + it * (32 * 144), bSrc + (long long)(it * 32) * ldb);      \
        }                                                                       \
    } while (0)

    STAGE(0, 0);
    CPC();

    for (int kb = 0; kb < NKB; kb++) {
        const int cur = kb & 1;
        if (kb + 1 < NKB) {
            STAGE(cur ^ 1, (kb + 1) << 6);
            CPC();
            CPW1();
        } else {
            CPW0();
        }
        __syncthreads();

        const __half* cA = (const __half*)(smem + cur * TILE_B);
        const __half* cB = (const __half*)(smem + (2 + cur) * TILE_B);
#pragma unroll
        for (int ks = 0; ks < 4; ks++) {
            const int kbase = ks * 16 + 2 * qc;
            uint32_t af[4][4];
#pragma unroll
            for (int mi = 0; mi < 4; mi++) {
                const int r0 = wm + mi * 16 + qr;
                af[mi][0] = *(const uint32_t*)(cA + r0 * SKH + kbase);
                af[mi][1] = *(const uint32_t*)(cA + (r0 + 8) * SKH + kbase);
                af[mi][2] = *(const uint32_t*)(cA + r0 * SKH + kbase + 8);
                af[mi][3] = *(const uint32_t*)(cA + (r0 + 8) * SKH + kbase + 8);
            }
            uint32_t bf[4][2];
#pragma unroll
            for (int ni = 0; ni < 4; ni++) {
                const int nr = wn + ni * 8 + qr;
                bf[ni][0] = *(const uint32_t*)(cB + nr * SKH + kbase);
                bf[ni][1] = *(const uint32_t*)(cB + nr * SKH + kbase + 8);
            }
#pragma unroll
            for (int mi = 0; mi < 4; mi++)
#pragma unroll
                for (int ni = 0; ni < 4; ni++)
                    mma16816(acc[mi][ni], af[mi], bf[ni]);
        }
        __syncthreads();
    }
#undef STAGE

    // ---- epilogue ----
#pragma unroll
    for (int mi = 0; mi < 4; mi++) {
        const int m = m0 + wm + mi * 16 + qr;
#pragma unroll
        for (int ni = 0; ni < 4; ni++) {
            const int nc = n0 + wn + ni * 8 + 2 * qc;
            float c0 = acc[mi][ni][0], c1 = acc[mi][ni][1];
            float c2 = acc[mi][ni][2], c3 = acc[mi][ni][3];
            if (EPI >= 1) {
                const float bx = bias[nc], by = bias[nc + 1];
                c0 += bx; c1 += by; c2 += bx; c3 += by;
            }
            if (EPI == 2) {
                c0 = fmaxf(c0, 0.f); c1 = fmaxf(c1, 0.f);
                c2 = fmaxf(c2, 0.f); c3 = fmaxf(c3, 0.f);
            }
            if (OUT == 0) {
                float* C = (float*)Cv + (long long)bz * sC;
                float2 lo; lo.x = c0; lo.y = c1;
                float2 hi; hi.x = c2; hi.y = c3;
                *(float2*)(C + (long long)m * ldc + nc) = lo;
                *(float2*)(C + (long long)(m + 8) * ldc + nc) = hi;
            } else if (OUT == 1) {
                __half* C = (__half*)Cv + (long long)bz * sC;
                *(__half2*)(C + (long long)m * ldc + nc) = __floats2half2_rn(c0, c1);
                *(__half2*)(C + (long long)(m + 8) * ldc + nc) = __floats2half2_rn(c2, c3);
            } else {
                __half* C = (__half*)Cv + (long long)bz * sC;
                C[(long long)nc * ldc + m]           = __float2half_rn(c0);
                C[(long long)(nc + 1) * ldc + m]     = __float2half_rn(c1);
                C[(long long)nc * ldc + m + 8]       = __float2half_rn(c2);
                C[(long long)(nc + 1) * ldc + m + 8] = __float2half_rn(c3);
            }
        }
    }
}

// ---------------- transpose + fp32->fp16 convert: src[R,C] -> dst[C,R] ----------------
__global__ void transpose_h(const float* __restrict__ src, __half* __restrict__ dst,
                            int R, int C)
{
    const int b = blockIdx.z;
    src += (long long)b * R * C;
    dst += (long long)b * R * C;
    const int r0 = blockIdx.y * 32;
    const int c0 = blockIdx.x * 32;
    __shared__ float t[32][33];
    const int tx = threadIdx.x, ty = threadIdx.y;   // 32 x 8
#pragma unroll
    for (int i = 0; i < 32; i += 8)
        t[ty + i][tx] = src[(long long)(r0 + ty + i) * C + c0 + tx];
    __syncthreads();
#pragma unroll
    for (int i = 0; i < 32; i += 8)
        dst[(long long)(c0 + ty + i) * R + r0 + tx] = __float2half_rn(t[tx][ty + i]);
}

// ---------------- softmax: fp32 scores -> fp16 attn ----------------
__global__ void softmax_kernel(const float* __restrict__ s, __half* __restrict__ sh,
                               float scale)
{
    const long long row = blockIdx.x;
    const float4* p = (const float4*)(s + row * SS);
    __half2* ph = (__half2*)(sh + row * SS);
    const int tid = threadIdx.x;
    __shared__ float red[256];

    float4 v[4];
    float mx = -INFINITY;
#pragma unroll
    for (int ii = 0; ii < 4; ii++) {
        v[ii] = p[tid + ii * 256];
        mx = fmaxf(mx, fmaxf(fmaxf(v[ii].x, v[ii].y), fmaxf(v[ii].z, v[ii].w)));
    }
    red[tid] = mx; __syncthreads();
    for (int o = 128; o > 0; o >>= 1) {
        if (tid < o) red[tid] = fmaxf(red[tid], red[tid + o]);
        __syncthreads();
    }
    mx = red[0];
    __syncthreads();

    float sum = 0.f;
#pragma unroll
    for (int ii = 0; ii < 4; ii++) {
        v[ii].x = __expf((v[ii].x - mx) * scale);
        v[ii].y = __expf((v[ii].y - mx) * scale);
        v[ii].z = __expf((v[ii].z - mx) * scale);
        v[ii].w = __expf((v[ii].w - mx) * scale);
        sum += v[ii].x + v[ii].y + v[ii].z + v[ii].w;
    }
    red[tid] = sum; __syncthreads();
    for (int o = 128; o > 0; o >>= 1) {
        if (tid < o) red[tid] += red[tid + o];
        __syncthreads();
    }
    const float inv = 1.f / red[0];
#pragma unroll
    for (int ii = 0; ii < 4; ii++) {
        const int e = (tid + ii * 256) * 2;
        ph[e]     = __floats2half2_rn(v[ii].x * inv, v[ii].y * inv);
        ph[e + 1] = __floats2half2_rn(v[ii].z * inv, v[ii].w * inv);
    }
}

// ---------------- reductions for the global norm ----------------
__device__ __forceinline__ void block_reduce_add2(float a, float b, int t, double* dst)
{
    __shared__ float sa[256], sb[256];
    sa[t] = a; sb[t] = b; __syncthreads();
    for (int o = 128; o > 0; o >>= 1) {
        if (t < o) { sa[t] += sa[t + o]; sb[t] += sb[t + o]; }
        __syncthreads();
    }
    if (t == 0) {
        atomicAdd(dst + 0, (double)sa[0]);
        atomicAdd(dst + 1, (double)sb[0]);
    }
}

__global__ void zero_acc_kernel()
{
    if (threadIdx.x < 32) g_acc[threadIdx.x] = 0.0;
}

// y[b,s,d] = x[b,d,s] + ao[b,s,d]; stats stage 0
__global__ void resid1_kernel(const float* __restrict__ x, const float* __restrict__ ao,
                              float* __restrict__ y)
{
    const int b  = blockIdx.z;
    const int s0 = blockIdx.x * 32;
    const int d0 = blockIdx.y * 32;
    __shared__ float xs[32][33];
    const int tx = threadIdx.x, ty = threadIdx.y;
    const int t = ty * 32 + tx;

    const float* xb = x + (long long)b * DD * SS;
#pragma unroll
    for (int i = 0; i < 32; i += 8)
        xs[ty + i][tx] = xb[(long long)(d0 + ty + i) * SS + s0 + tx];
    __syncthreads();

    float ls = 0.f, lq = 0.f;
#pragma unroll
    for (int i = 0; i < 32; i += 8) {
        long long off = ((long long)b * SS + s0 + ty + i) * DD + d0 + tx;
        float vv = ao[off] + xs[tx][ty + i];
        y[off] = vv;
        ls += vv;
        lq += vv * vv;
    }
    block_reduce_add2(ls, lq, t, g_acc + 2 * b);
}

// normalize y in place (fp32) + write fp16 copy
__global__ void apply1_kernel(float* __restrict__ y, __half* __restrict__ yh)
{
    const int b = blockIdx.y;
    const double sum = g_acc[2 * b], sq = g_acc[2 * b + 1];
    const double NE = (double)SS * DD;
    const double mean = sum / NE;
    double var = sq - NE * mean * mean;
    if (var < 0.0) var = 0.0;
    const float inv = (float)(1.0 / (sqrt(var) + 1e-7));
    const float fm = (float)mean;

    float4* y4 = ((float4*)y) + (long long)b * (SS * DD / 4);
    __half2* yh2 = ((__half2*)yh) + (long long)b * (SS * DD / 2);
    const long long i = (long long)blockIdx.x * 256 + threadIdx.x;  // grid.x = 2048
    float4 vv = y4[i];
    vv.x = (vv.x - fm) * inv; vv.y = (vv.y - fm) * inv;
    vv.z = (vv.z - fm) * inv; vv.w = (vv.w - fm) * inv;
    y4[i] = vv;
    yh2[i * 2]     = __floats2half2_rn(vv.x, vv.y);
    yh2[i * 2 + 1] = __floats2half2_rn(vv.z, vv.w);
}

// h2 <- post + h2 ; stats stage 1
__global__ void resid2_kernel(const float* __restrict__ post, float* __restrict__ h2)
{
    const int b = blockIdx.y;
    const float4* p4 = ((const float4*)post) + (long long)b * (SS * DD / 4);
    float4*       h4 = ((float4*)h2)   + (long long)b * (SS * DD / 4);
    const long long i = (long long)blockIdx.x * 256 + threadIdx.x;
    float4 a = p4[i], cc = h4[i];
    a.x += cc.x; a.y += cc.y; a.z += cc.z; a.w += cc.w;
    h4[i] = a;
    float ls = a.x + a.y + a.z + a.w;
    float lq = a.x * a.x + a.y * a.y + a.z * a.z + a.w * a.w;
    block_reduce_add2(ls, lq, threadIdx.x, g_acc + 16 + 2 * b);
}

// out[b,d,s] = (y2[b,s,d] - mean) * inv
__global__ void apply2t_kernel(const float* __restrict__ y2, float* __restrict__ out)
{
    const int b = blockIdx.z;
    const double sum = g_acc[16 + 2 * b], sq = g_acc[16 + 2 * b + 1];
    const double NE = (double)SS * DD;
    const double mean = sum / NE;
    double var = sq - NE * mean * mean;
    if (var < 0.0) var = 0.0;
    const float inv = (float)(1.0 / (sqrt(var) + 1e-7));
    const float fm = (float)mean;

    const int s0 = blockIdx.x * 32;
    const int d0 = blockIdx.y * 32;
    __shared__ float ys[32][33];
    const int tx = threadIdx.x, ty = threadIdx.y;

#pragma unroll
    for (int i = 0; i < 32; i += 8)
        ys[ty + i][tx] = y2[((long long)b * SS + s0 + ty + i) * DD + d0 + tx];
    __syncthreads();
#pragma unroll
    for (int i = 0; i < 32; i += 8)
        out[((long long)b * DD + d0 + ty + i) * SS + s0 + tx] =
            (ys[tx][ty + i] - fm) * inv;
}

// ---------------- host-side orchestration ----------------
template <typename T>
static T* sym(const void* symbol)
{
    void* p = nullptr;
    cudaGetSymbolAddress(&p, symbol);
    return (T*)p;
}

extern "C" void kernel_launch(void* const* d_in, const int* in_sizes, int n_in,
                              void* d_out, int out_size)
{
    const float* x  = (const float*)d_in[0];
    const float* Wq = (const float*)d_in[1];
    const float* Wk = (const float*)d_in[2];
    const float* Wv = (const float*)d_in[3];
    const float* Wo = (const float*)d_in[4];
    const float* W1 = (const float*)d_in[5];
    const float* b1 = (const float*)d_in[6];
    const float* W2 = (const float*)d_in[7];
    const float* b2 = (const float*)d_in[8];
    float* out = (float*)d_out;

    float*  ps   = sym<float>((const void*)g_s);
    float*  pao  = sym<float>((const void*)g_ao);
    float*  py   = sym<float>((const void*)g_y);
    float*  ph2  = sym<float>((const void*)g_h2);
    __half* pxh  = sym<__half>((const void*)g_xh);
    __half* pqh  = sym<__half>((const void*)g_qh);
    __half* pkh  = sym<__half>((const void*)g_kh);
    __half* pvt  = sym<__half>((const void*)g_vt);
    __half* psh  = sym<__half>((const void*)g_sh);
    __half* pt1h = sym<__half>((const void*)g_t1h);
    __half* pyh  = sym<__half>((const void*)g_yh);
    __half* ph1h = sym<__half>((const void*)g_h1h);
    __half* pwqT = sym<__half>((const void*)g_wqT);
    __half* pwkT = sym<__half>((const void*)g_wkT);
    __half* pwvT = sym<__half>((const void*)g_wvT);
    __half* pwoT = sym<__half>((const void*)g_woT);
    __half* pw1T = sym<__half>((const void*)g_w1T);
    __half* pw2T = sym<__half>((const void*)g_w2T);

    const long long sSD = (long long)SS * DD;
    const long long sSS = (long long)SS * SS;
    const long long sSF = (long long)SS * FF;
    const long long sDS = (long long)DD * SS;

    cudaFuncSetAttribute(gemm_h<0, 0>, cudaFuncAttributeMaxDynamicSharedMemorySize, SMEMB);
    cudaFuncSetAttribute(gemm_h<0, 1>, cudaFuncAttributeMaxDynamicSharedMemorySize, SMEMB);
    cudaFuncSetAttribute(gemm_h<0, 2>, cudaFuncAttributeMaxDynamicSharedMemorySize, SMEMB);
    cudaFuncSetAttribute(gemm_h<2, 1>, cudaFuncAttributeMaxDynamicSharedMemorySize, SMEMB);
    cudaFuncSetAttribute(gemm_h<1, 0>, cudaFuncAttributeMaxDynamicSharedMemorySize, SMEMB);

    zero_acc_kernel<<<1, 32>>>();

    // pre-pass: fp16 transposed operands
    dim3 tblk(32, 8);
    transpose_h<<<dim3(SS / 32, DD / 32, BB), tblk>>>(x,  pxh,  DD, SS); // x[b]:[D,S]->[S,D]
    transpose_h<<<dim3(DD / 32, DD / 32, 1), tblk>>>(Wq, pwqT, DD, DD);
    transpose_h<<<dim3(DD / 32, DD / 32, 1), tblk>>>(Wk, pwkT, DD, DD);
    transpose_h<<<dim3(DD / 32, DD / 32, 1), tblk>>>(Wv, pwvT, DD, DD);
    transpose_h<<<dim3(DD / 32, DD / 32, 1), tblk>>>(Wo, pwoT, DD, DD);
    transpose_h<<<dim3(FF / 32, DD / 32, 1), tblk>>>(W1, pw1T, DD, FF); // [D,F]->[F,D]
    transpose_h<<<dim3(DD / 32, FF / 32, 1), tblk>>>(W2, pw2T, FF, DD); // [F,D]->[D,F]

    dim3 blk(256);
    dim3 gNarrow(DD / 128, SS / 128, BB);   // (4,32,8)
    dim3 gScore(SS / 128, SS / 128, BB);    // (32,32,8)
    dim3 gFFN(FF / 128, SS / 128, BB);      // (16,32,8)

    // q,k = xh @ WT  (fp16 out)
    gemm_h<0, 1><<<gNarrow, blk, SMEMB>>>(pxh, pwqT, nullptr, pqh,
        DD, DD, DD, DD, sSD, 0, sSD);
    gemm_h<0, 1><<<gNarrow, blk, SMEMB>>>(pxh, pwkT, nullptr, pkh,
        DD, DD, DD, DD, sSD, 0, sSD);
    // v = xh @ WvT (fp16 out, transposed to [D,S])
    gemm_h<0, 2><<<gNarrow, blk, SMEMB>>>(pxh, pwvT, nullptr, pvt,
        DD, DD, DD, SS, sSD, 0, sDS);

    // scores = q @ k^T (fp32 out)
    gemm_h<0, 0><<<gScore, blk, SMEMB>>>(pqh, pkh, nullptr, ps,
        DD, DD, DD, SS, sSD, sSD, sSS);

    softmax_kernel<<<BB * SS, 256>>>(ps, psh, 0.04419417382415922f /* 1/sqrt(512) */);

    // t1 = attn @ v  (A=[S,S], B=vT[D,S]; fp16 out)
    gemm_h<0, 1><<<gNarrow, blk, SMEMB>>>(psh, pvt, nullptr, pt1h,
        SS, SS, SS, DD, sSS, sDS, sSD);

    // ao = t1 @ Wo (fp32 out)
    gemm_h<0, 0><<<gNarrow, blk, SMEMB>>>(pt1h, pwoT, nullptr, pao,
        DD, DD, DD, DD, sSD, 0, sSD);

    dim3 rgrid(SS / 32, DD / 32, BB);
    resid1_kernel<<<rgrid, tblk>>>(x, pao, py);
    apply1_kernel<<<dim3(2048, BB), 256>>>(py, pyh);

    // FFN
    gemm_h<2, 1><<<gFFN, blk, SMEMB>>>(pyh, pw1T, b1, ph1h,
        DD, DD, DD, FF, sSD, 0, sSF);
    gemm_h<1, 0><<<gNarrow, blk, SMEMB>>>(ph1h, pw2T, b2, ph2,
        FF, FF, FF, DD, sSF, 0, sSD);

    resid2_kernel<<<dim3(2048, BB), 256>>>(py, ph2);
    apply2t_kernel<<<rgrid, tblk>>>(ph2, out);

    (void)in_sizes; (void)n_in; (void)out_size;
}